// round 3
// baseline (speedup 1.0000x reference)
#include <cuda_runtime.h>
#include <math.h>

// Fixed problem shapes
#define N_NODES 50000
#define N_EDGES 3200000
#define F_IN    8      // 4*NT
#define H1      64
#define NPB     8      // nodes per block (50000 % 8 == 0)
#define NBLK    (N_NODES / NPB)   // 6250
#define TPB     256
#define N_ITERS 8
#define FULLM   0xffffffffu

// ---------------- device scratch (static; no allocation allowed) ----------------
__device__ float g_x0[N_NODES * F_IN];
__device__ float g_x1[N_NODES * F_IN];
__device__ int   g_hist[N_NODES];
__device__ int   g_rowptr[N_NODES + 1];
__device__ int   g_offs[N_NODES];
__device__ int   g_srcs[N_EDGES];
__device__ int   g_dsts[N_EDGES];
__device__ float g_eas[(long long)N_EDGES * 8];   // sorted edge_attr, padded to 8 floats

// prepared weights for the edge MLP
__device__ float g_W1[H1 * 16];   // [j][k]: k<13 -> w1_0[k][j], k==13 -> b1_0[j], else 0
__device__ float g_W2T[H1 * H1];  // [j][k] = w1_1[k][j]
__device__ float g_b11[H1];

// ---------------- weight preparation ----------------
__global__ void prep_kernel(const float* __restrict__ w10, const float* __restrict__ b10,
                            const float* __restrict__ w11, const float* __restrict__ b11) {
    int t = blockIdx.x * blockDim.x + threadIdx.x;
    if (t < H1 * 16) {
        int j = t >> 4, k = t & 15;
        float v = 0.f;
        if (k < 13)       v = w10[k * H1 + j];
        else if (k == 13) v = b10[j];
        g_W1[t] = v;
    }
    if (t < H1 * H1) {
        int j = t >> 6, k = t & 63;
        g_W2T[t] = w11[k * H1 + j];
    }
    if (t < H1) g_b11[t] = b11[t];
}

// ---------------- sorting pipeline (runs once per launch) ----------------
__global__ void zero_hist_kernel() {
    int i = blockIdx.x * blockDim.x + threadIdx.x;
    if (i < N_NODES) g_hist[i] = 0;
}

__global__ void hist_kernel(const int* __restrict__ eidx) {
    int i = blockIdx.x * blockDim.x + threadIdx.x;
    if (i < N_EDGES) atomicAdd(&g_hist[eidx[N_EDGES + i]], 1);
}

// single-block exclusive scan over g_hist -> g_rowptr, g_offs
__global__ void scan_kernel() {
    __shared__ int swarp[16];
    __shared__ int srun;
    int tid = threadIdx.x, lane = tid & 31, wid = tid >> 5;
    if (tid == 0) srun = 0;
    __syncthreads();
    const int CH = (N_NODES + 511) / 512;
    for (int c = 0; c < CH; c++) {
        int i = c * 512 + tid;
        int orig = (i < N_NODES) ? g_hist[i] : 0;
        int v = orig;
#pragma unroll
        for (int off = 1; off < 32; off <<= 1) {
            int n = __shfl_up_sync(FULLM, v, off);
            if (lane >= off) v += n;
        }
        if (lane == 31) swarp[wid] = v;
        __syncthreads();
        if (wid == 0) {
            int w = (lane < 16) ? swarp[lane] : 0;
#pragma unroll
            for (int off = 1; off < 16; off <<= 1) {
                int n = __shfl_up_sync(FULLM, w, off);
                if (lane >= off) w += n;
            }
            if (lane < 16) swarp[lane] = w;
        }
        __syncthreads();
        int base = (wid > 0) ? swarp[wid - 1] : 0;
        int incl = v + base;           // inclusive within chunk
        int run = srun;
        int excl = run + incl - orig;
        if (i < N_NODES) { g_rowptr[i] = excl; g_offs[i] = excl; }
        __syncthreads();
        if (tid == 511) srun = run + incl;
        __syncthreads();
    }
    if (threadIdx.x == 0) g_rowptr[N_NODES] = N_EDGES;
}

__global__ void scatter_kernel(const float* __restrict__ ea, const int* __restrict__ eidx) {
    int i = blockIdx.x * blockDim.x + threadIdx.x;
    if (i >= N_EDGES) return;
    int d = eidx[N_EDGES + i];
    int pos = atomicAdd(&g_offs[d], 1);
    g_srcs[pos] = eidx[i];
    g_dsts[pos] = d;
    const float* a = ea + (long long)i * 5;
    float* o = g_eas + (long long)pos * 8;
    o[0] = a[0]; o[1] = a[1]; o[2] = a[2]; o[3] = a[3]; o[4] = a[4];
}

// ---------------- fused iteration kernel ----------------
// Block owns nodes [8b, 8b+8) and their contiguous dst-sorted edge range.
// Edge MLP -> warp segmented suffix-max -> leader smem atomicMax -> node MLP.
__global__ __launch_bounds__(TPB, 2)
void fused_kernel(const float* __restrict__ x, float* __restrict__ y,
                  const float* __restrict__ w20, const float* __restrict__ b20,
                  const float* __restrict__ w21, const float* __restrict__ b21) {
    __shared__ float sW1[H1 * 16];
    __shared__ float sW2[H1 * H1];
    __shared__ float sb1[H1];
    __shared__ float sW3[72 * 32];
    __shared__ float sb20[32];
    __shared__ float sW4[32 * 5];
    __shared__ float sb21[8];
    __shared__ int   saccum[NPB * H1];
    __shared__ float sxn[NPB * F_IN];
    __shared__ float sh2[NPB * 32];
    __shared__ float so[NPB * 5];

    int tid = threadIdx.x;
    for (int i = tid; i < H1 * 16; i += TPB) sW1[i] = g_W1[i];
    for (int i = tid; i < H1 * H1; i += TPB) sW2[i] = g_W2T[i];
    if (tid < H1) sb1[tid] = g_b11[tid];
    for (int i = tid; i < 72 * 32; i += TPB) sW3[i] = w20[i];
    if (tid < 32) sW4[tid * 5 + 0] = w21[tid * 5 + 0];  // dummy to keep layout simple below
    for (int i = tid; i < 32 * 5; i += TPB) sW4[i] = w21[i];
    if (tid < 32) sb20[tid] = b20[tid];
    if (tid < 5)  sb21[tid] = b21[tid];
    for (int i = tid; i < NPB * H1; i += TPB) saccum[i] = 0;
    int nodeBase = blockIdx.x * NPB;
    if (tid < NPB * F_IN) sxn[tid] = x[nodeBase * F_IN + tid];
    __syncthreads();

    const int e0 = g_rowptr[nodeBase];
    const int e1 = g_rowptr[nodeBase + NPB];
    const int lane = tid & 31;

    for (int eb = e0; eb < e1; eb += TPB) {
        int e = eb + tid;
        bool act = e < e1;
        int dstL = 0x7fffffff;
        float t[16];
#pragma unroll
        for (int k = 0; k < 16; k++) t[k] = 0.f;
        t[13] = 1.f;
        if (act) {
            int src = g_srcs[e];
            dstL = g_dsts[e] - nodeBase;
            const float4* xr = reinterpret_cast<const float4*>(x + (long long)src * F_IN);
            float4 xa = __ldg(xr);
            float4 xb = __ldg(xr + 1);
            t[0] = xa.x; t[1] = xa.y; t[2] = xa.z; t[3] = xa.w;
            t[4] = xb.x; t[5] = xb.y; t[6] = xb.z; t[7] = xb.w;
            const float* a = g_eas + (long long)e * 8;
            float4 a4 = *reinterpret_cast<const float4*>(a);
            t[8] = a4.x; t[9] = a4.y; t[10] = a4.z; t[11] = a4.w;
            t[12] = a[4];
        }

        // GEMM1: h[j] = relu(sum_k t[k] * W1[j][k])  (bias folded)
        float h[H1];
#pragma unroll
        for (int j = 0; j < H1; j++) {
            const float4* w = reinterpret_cast<const float4*>(sW1 + j * 16);
            float acc = 0.f;
#pragma unroll
            for (int q = 0; q < 4; q++) {
                float4 wv = w[q];
                acc += t[4 * q + 0] * wv.x;
                acc += t[4 * q + 1] * wv.y;
                acc += t[4 * q + 2] * wv.z;
                acc += t[4 * q + 3] * wv.w;
            }
            h[j] = fmaxf(acc, 0.f);
        }

        // segment masks (lanes are dst-sorted)
        int d1 = __shfl_down_sync(FULLM, dstL, 1);  bool s1 = (lane <= 30) && (d1 == dstL);
        int d2 = __shfl_down_sync(FULLM, dstL, 2);  bool s2 = (lane <= 29) && (d2 == dstL);
        int d4 = __shfl_down_sync(FULLM, dstL, 4);  bool s4 = (lane <= 27) && (d4 == dstL);
        int d8 = __shfl_down_sync(FULLM, dstL, 8);  bool s8 = (lane <= 23) && (d8 == dstL);
        int d16 = __shfl_down_sync(FULLM, dstL, 16); bool s16 = (lane <= 15) && (d16 == dstL);
        int dp = __shfl_up_sync(FULLM, dstL, 1);
        bool doAtom = ((lane == 0) || (dp != dstL)) && act;
        int abase = dstL * H1;

        // GEMM2 in groups of 8 + segmented suffix-max + leader smem atomics
#pragma unroll 1
        for (int jb = 0; jb < H1; jb += 8) {
            float m[8];
#pragma unroll
            for (int jj = 0; jj < 8; jj++) {
                const float4* w = reinterpret_cast<const float4*>(sW2 + (jb + jj) * H1);
                float acc = sb1[jb + jj];
#pragma unroll
                for (int q = 0; q < 16; q++) {
                    float4 wv = w[q];
                    acc += h[4 * q + 0] * wv.x;
                    acc += h[4 * q + 1] * wv.y;
                    acc += h[4 * q + 2] * wv.z;
                    acc += h[4 * q + 3] * wv.w;
                }
                m[jj] = fmaxf(acc, 0.f);
            }
#pragma unroll
            for (int jj = 0; jj < 8; jj++) {
                float v = m[jj], v2;
                v2 = __shfl_down_sync(FULLM, v, 1);  v = fmaxf(v, s1 ? v2 : 0.f);
                v2 = __shfl_down_sync(FULLM, v, 2);  v = fmaxf(v, s2 ? v2 : 0.f);
                v2 = __shfl_down_sync(FULLM, v, 4);  v = fmaxf(v, s4 ? v2 : 0.f);
                v2 = __shfl_down_sync(FULLM, v, 8);  v = fmaxf(v, s8 ? v2 : 0.f);
                v2 = __shfl_down_sync(FULLM, v, 16); v = fmaxf(v, s16 ? v2 : 0.f);
                if (doAtom) atomicMax(&saccum[abase + jb + jj], __float_as_int(v));
            }
        }
    }
    __syncthreads();

    // ---- node MLP for the block's 8 nodes ----
    {
        int s = tid >> 5, j = tid & 31;   // warp s handles node s
        float acc = sb20[j];
#pragma unroll
        for (int k = 0; k < F_IN; k++)
            acc += sxn[s * F_IN + k] * sW3[k * 32 + j];
#pragma unroll 8
        for (int k = 0; k < H1; k++)
            acc += __int_as_float(saccum[s * H1 + k]) * sW3[(F_IN + k) * 32 + j];
        sh2[s * 32 + j] = fmaxf(acc, 0.f);
    }
    __syncthreads();
    if (tid < NPB * 5) {
        int s = tid / 5, jo = tid % 5;
        float acc = sb21[jo];
#pragma unroll
        for (int k = 0; k < 32; k++)
            acc += sh2[s * 32 + k] * sW4[k * 5 + jo];
        so[tid] = acc;
    }
    __syncthreads();
    if (tid < NPB) {
        int n = nodeBase + tid;
        float l  = so[tid * 5 + 0];
        float c1 = so[tid * 5 + 1];
        float c2 = so[tid * 5 + 2];
        float c3 = so[tid * 5 + 3];
        float c4 = so[tid * 5 + 4];
        float nor = sqrtf(c1 * c1 + c2 * c2 + c3 * c3 + c4 * c4);
        float dd = fmaxf(1.f, nor);
        float* yr = y + (long long)n * F_IN;
        yr[0] = l;
        yr[1] = c1 / dd;
        yr[2] = c2 / dd;
        yr[3] = c3 / dd;
        yr[4] = c4 / dd;
        yr[5] = sxn[tid * F_IN + 0];
        yr[6] = sxn[tid * F_IN + 1];
        yr[7] = sxn[tid * F_IN + 2];
    }
}

// ---------------- host ----------------
extern "C" void kernel_launch(void* const* d_in, const int* in_sizes, int n_in,
                              void* d_out, int out_size) {
    const float* x_in = (const float*)d_in[0];
    const float* ea   = (const float*)d_in[1];
    const int*   ei   = (const int*)d_in[2];
    const float* w10  = (const float*)d_in[3];
    const float* b10  = (const float*)d_in[4];
    const float* w11  = (const float*)d_in[5];
    const float* b11  = (const float*)d_in[6];
    const float* w20  = (const float*)d_in[7];
    const float* b20  = (const float*)d_in[8];
    const float* w21  = (const float*)d_in[9];
    const float* b21  = (const float*)d_in[10];

    float* xb[2];
    cudaGetSymbolAddress((void**)&xb[0], g_x0);
    cudaGetSymbolAddress((void**)&xb[1], g_x1);

    prep_kernel<<<16, 256>>>(w10, b10, w11, b11);
    zero_hist_kernel<<<(N_NODES + 255) / 256, 256>>>();
    hist_kernel<<<(N_EDGES + 255) / 256, 256>>>(ei);
    scan_kernel<<<1, 512>>>();
    scatter_kernel<<<(N_EDGES + 255) / 256, 256>>>(ea, ei);

    const float* xin = x_in;
    for (int it = 0; it < N_ITERS; it++) {
        float* yout = (it == N_ITERS - 1) ? (float*)d_out : xb[it & 1];
        fused_kernel<<<NBLK, TPB>>>(xin, yout, w20, b20, w21, b21);
        xin = yout;
    }
}